// round 16
// baseline (speedup 1.0000x reference)
#include <cuda_runtime.h>
#include <cuda_bf16.h>
#include <cuda_fp16.h>
#include <cstdint>

// GraphSAGE 2-layer + head.  (Resubmit of R15 — infra failure, never ran.)
// Edge phase: CSR build (low-word int32 decode) + warp-per-node fp16-gather
// mean aggregation with PREDICATED batch-8 gathers (no serial remainder tail).
// Layer GEMMs: persistent mma.sync bf16x3, B images loaded once, A
// double-buffered. Head: persistent bf16x3 mma on padded 64-row Wout.

#define MAXN 100000
#define MAXE 1600000
#define DIM  128
#define SCAN_BS 1024
#define MAX_BLKS 256

typedef unsigned int u32;
typedef unsigned long long u64;

// ---- bf16 image layout: row pitch 136 bf16 = 272B.
#define PITCHB 272
#define AIMG 17408                        // 64-row image (hi or lo)
#define BIMG 34816                        // 128-row image
#define PA(buf) ((buf) * 2 * AIMG)
#define PB (4 * AIMG)                     // 69632
#define SMEM_PGEMM (PB + 4 * BIMG)        // 208896
// persistent head smem: A buf0 hi/lo, A buf1 hi/lo, B hi/lo (64-row)
#define H_B (4 * AIMG)
#define SMEM_HEAD (6 * AIMG)              // 104448

__device__ int    g_is64;
__device__ int    g_deg[MAXN];
__device__ int    g_off[MAXN + 1];
__device__ int    g_cur[MAXN];
__device__ int    g_csr[MAXE];
__device__ int    g_part[MAX_BLKS];
__device__ float4 g_mean4[(size_t)MAXN * 32];
__device__ float4 g_h14[(size_t)MAXN * 32];
__device__ float4 g_h24[(size_t)MAXN * 32];
__device__ uint2  g_xh[(size_t)MAXN * 32];     // fp16 image of x
__device__ uint2  g_h1h[(size_t)MAXN * 32];    // fp16 image of h1
__device__ uint4  g_wimg[10][BIMG / 16];       // 0..7 layer W, 8..9 Wout(64pad)

// ---------------------------------------------------------------------------
__device__ __forceinline__ u32 smem_u32(const void* p) {
    u32 a;
    asm("{ .reg .u64 t; cvta.to.shared.u64 t, %1; cvt.u32.u64 %0, t; }"
        : "=r"(a) : "l"(p));
    return a;
}
__device__ __forceinline__ void ldsm4(u32& r0, u32& r1, u32& r2, u32& r3, u32 a) {
    asm volatile("ldmatrix.sync.aligned.m8n8.x4.shared.b16 {%0,%1,%2,%3}, [%4];"
                 : "=r"(r0), "=r"(r1), "=r"(r2), "=r"(r3) : "r"(a));
}
__device__ __forceinline__ void mma_bf16(float* d, const u32* a, u32 b0, u32 b1) {
    asm volatile(
        "mma.sync.aligned.m16n8k16.row.col.f32.bf16.bf16.f32 "
        "{%0,%1,%2,%3},{%4,%5,%6,%7},{%8,%9},{%0,%1,%2,%3};"
        : "+f"(d[0]), "+f"(d[1]), "+f"(d[2]), "+f"(d[3])
        : "r"(a[0]), "r"(a[1]), "r"(a[2]), "r"(a[3]), "r"(b0), "r"(b1));
}
__device__ __forceinline__ void cpa16(u32 s, const void* g) {
    asm volatile("cp.async.cg.shared.global [%0], [%1], 16;" :: "r"(s), "l"(g));
}
__device__ __forceinline__ void cpa_commit_wait() {
    asm volatile("cp.async.commit_group;" ::: "memory");
    asm volatile("cp.async.wait_group 0;" ::: "memory");
}
__device__ __forceinline__ void split2(float f0, float f1, u32& hp, u32& lp) {
    __nv_bfloat16 h0 = __float2bfloat16_rn(f0);
    __nv_bfloat16 h1 = __float2bfloat16_rn(f1);
    __nv_bfloat16 l0 = __float2bfloat16_rn(f0 - __bfloat162float(h0));
    __nv_bfloat16 l1 = __float2bfloat16_rn(f1 - __bfloat162float(h1));
    __nv_bfloat162 hh = __halves2bfloat162(h0, h1);
    __nv_bfloat162 ll = __halves2bfloat162(l0, l1);
    hp = *reinterpret_cast<u32*>(&hh);
    lp = *reinterpret_cast<u32*>(&ll);
}
__device__ __forceinline__ void split8(const float* f, u32* hp, u32* lp) {
    #pragma unroll
    for (int i = 0; i < 4; i++) split2(f[2 * i], f[2 * i + 1], hp[i], lp[i]);
}
__device__ __forceinline__ u32 h2bits(__half2 h) {
    return *reinterpret_cast<u32*>(&h);
}

// convert one 64-row fp32 slab -> bf16 hi/lo images at smem+abase / +AIMG
__device__ __forceinline__ void conv_slab(const float* __restrict__ A, int row0,
                                          int n, char* smem, int abase,
                                          int tid, int nthr) {
    for (int g = tid; g < 1024; g += nthr) {
        int row = g >> 4;
        int col8 = (g & 15) << 3;
        int gr = row0 + row;
        float f[8] = {0.f, 0.f, 0.f, 0.f, 0.f, 0.f, 0.f, 0.f};
        if (gr < n) {
            float4 v0 = *reinterpret_cast<const float4*>(&A[(size_t)gr * 128 + col8]);
            float4 v1 = *reinterpret_cast<const float4*>(&A[(size_t)gr * 128 + col8 + 4]);
            f[0] = v0.x; f[1] = v0.y; f[2] = v0.z; f[3] = v0.w;
            f[4] = v1.x; f[5] = v1.y; f[6] = v1.z; f[7] = v1.w;
        }
        u32 hp[4], lp[4];
        split8(f, hp, lp);
        int off = row * PITCHB + col8 * 2;
        *reinterpret_cast<uint4*>(smem + abase + off) =
            make_uint4(hp[0], hp[1], hp[2], hp[3]);
        *reinterpret_cast<uint4*>(smem + abase + AIMG + off) =
            make_uint4(lp[0], lp[1], lp[2], lp[3]);
    }
}

// ---------------------------------------------------------------------------
// prep: dtype detect (block 0) + clear deg + x->fp16 conversion, one kernel.
// ---------------------------------------------------------------------------
__global__ void prep_kernel(const int* __restrict__ w, const float4* __restrict__ x,
                            int e, int n, int n16) {
    int i = blockIdx.x * blockDim.x + threadIdx.x;
    if (blockIdx.x == 0) {
        __shared__ int bad;
        if (threadIdx.x == 0) bad = 0;
        __syncthreads();
        int nchk = (e < 256) ? e : 256;
        if (threadIdx.x < nchk && w[2 * threadIdx.x + 1] != 0) atomicOr(&bad, 1);
        __syncthreads();
        if (threadIdx.x == 0) g_is64 = bad ? 0 : 1;
    }
    if (i < n) g_deg[i] = 0;
    if (i < n16) {
        float4 v0 = x[2 * i], v1 = x[2 * i + 1];
        uint2 o0, o1;
        o0.x = h2bits(__floats2half2_rn(v0.x, v0.y));
        o0.y = h2bits(__floats2half2_rn(v0.z, v0.w));
        o1.x = h2bits(__floats2half2_rn(v1.x, v1.y));
        o1.y = h2bits(__floats2half2_rn(v1.z, v1.w));
        g_xh[2 * i] = o0;
        g_xh[2 * i + 1] = o1;
    }
}

// ---------------------------------------------------------------------------
// hist / scatter: decode via low int32 words (int64 payload fits in 32 bits)
// ---------------------------------------------------------------------------
__global__ void hist_kernel(const int* __restrict__ w32, int e, int n) {
    int i = blockIdx.x * blockDim.x + threadIdx.x;
    if (i >= e) return;
    int d = g_is64 ? w32[2 * (e + i)] : w32[e + i];
    if ((unsigned)d < (unsigned)n) atomicAdd(&g_deg[d], 1);
}

__global__ void scatter_kernel(const int* __restrict__ w32, int e, int n) {
    int i = blockIdx.x * blockDim.x + threadIdx.x;
    if (i >= e) return;
    int s, d;
    if (g_is64) {
        s = w32[2 * i];
        d = w32[2 * (e + i)];
    } else {
        s = w32[i];
        d = w32[e + i];
    }
    if ((unsigned)d >= (unsigned)n || (unsigned)s >= (unsigned)n) return;
    int pos = atomicAdd(&g_cur[d], 1);
    g_csr[pos] = s;
}

// ---------------------------------------------------------------------------
// 3-phase parallel scan
// ---------------------------------------------------------------------------
__global__ void scan_part_kernel(int n) {
    __shared__ int ws[32];
    int i = blockIdx.x * SCAN_BS + threadIdx.x;
    int lane = threadIdx.x & 31, wid = threadIdx.x >> 5;
    int v = (i < n) ? g_deg[i] : 0;
    #pragma unroll
    for (int d = 16; d; d >>= 1) v += __shfl_down_sync(0xffffffffu, v, d);
    if (lane == 0) ws[wid] = v;
    __syncthreads();
    if (wid == 0) {
        int t = ws[lane];
        #pragma unroll
        for (int d = 16; d; d >>= 1) t += __shfl_down_sync(0xffffffffu, t, d);
        if (lane == 0) g_part[blockIdx.x] = t;
    }
}

__global__ void scan_top_kernel(int nblk, int n) {
    __shared__ int wsum[32];
    int tid = threadIdx.x, lane = tid & 31, wid = tid >> 5;
    int v = (tid < nblk) ? g_part[tid] : 0;
    int s = v;
    #pragma unroll
    for (int d = 1; d < 32; d <<= 1) {
        int t = __shfl_up_sync(0xffffffffu, s, d);
        if (lane >= d) s += t;
    }
    if (lane == 31) wsum[wid] = s;
    __syncthreads();
    if (wid == 0) {
        int w2 = wsum[lane];
        #pragma unroll
        for (int d = 1; d < 32; d <<= 1) {
            int t = __shfl_up_sync(0xffffffffu, w2, d);
            if (lane >= d) w2 += t;
        }
        wsum[lane] = w2;
    }
    __syncthreads();
    int warp_base = (wid > 0) ? wsum[wid - 1] : 0;
    int incl = warp_base + s;
    if (tid < nblk) g_part[tid] = incl - v;
    if (tid == 1023) g_off[n] = incl;
}

__global__ void scan_apply_kernel(int n) {
    __shared__ int wsum[32];
    int tid = threadIdx.x, lane = tid & 31, wid = tid >> 5;
    int i = blockIdx.x * SCAN_BS + tid;
    int v = (i < n) ? g_deg[i] : 0;
    int s = v;
    #pragma unroll
    for (int d = 1; d < 32; d <<= 1) {
        int t = __shfl_up_sync(0xffffffffu, s, d);
        if (lane >= d) s += t;
    }
    if (lane == 31) wsum[wid] = s;
    __syncthreads();
    if (wid == 0) {
        int w2 = wsum[lane];
        #pragma unroll
        for (int d = 1; d < 32; d <<= 1) {
            int t = __shfl_up_sync(0xffffffffu, w2, d);
            if (lane >= d) w2 += t;
        }
        wsum[lane] = w2;
    }
    __syncthreads();
    int warp_base = (wid > 0) ? wsum[wid - 1] : 0;
    int excl = g_part[blockIdx.x] + warp_base + s - v;
    if (i < n) { g_off[i] = excl; g_cur[i] = excl; }
}

// ---------------------------------------------------------------------------
// mean aggregation: one warp per node. PREDICATED batch-8 gathers — every
// batch issues 8 independent loads (clamped index), masked accumulation.
// No serial remainder tail.
// ---------------------------------------------------------------------------
__global__ void aggregate_kernel(const uint2* __restrict__ feat,
                                 float4* __restrict__ outp, int n) {
    int w = (blockIdx.x * blockDim.x + threadIdx.x) >> 5;
    int lane = threadIdx.x & 31;
    if (w >= n) return;
    int s0 = g_off[w], s1 = g_off[w + 1];
    float4 a = make_float4(0.f, 0.f, 0.f, 0.f);
    for (int e = s0; e < s1; e += 8) {
        uint2 u[8];
        #pragma unroll
        for (int q = 0; q < 8; q++) {
            int idx = g_csr[(e + q < s1) ? (e + q) : s0];
            u[q] = feat[(size_t)idx * 32 + lane];
        }
        #pragma unroll
        for (int q = 0; q < 8; q++) {
            if (e + q < s1) {
                float2 f0 = __half22float2(*reinterpret_cast<__half2*>(&u[q].x));
                float2 f1 = __half22float2(*reinterpret_cast<__half2*>(&u[q].y));
                a.x += f0.x; a.y += f0.y; a.z += f1.x; a.w += f1.y;
            }
        }
    }
    int deg = s1 - s0;
    float inv = 1.0f / (float)(deg > 1 ? deg : 1);
    a.x *= inv; a.y *= inv; a.z *= inv; a.w *= inv;
    outp[(size_t)w * 32 + lane] = a;
}

// ---------------------------------------------------------------------------
// weight prep: bf16 hi/lo pitch-136 images. blocks 0-3: 128x128 layer
// weights; block 4: Wout (40x128) zero-padded to 64 rows.
// ---------------------------------------------------------------------------
__global__ void wprep_kernel(const float* __restrict__ Wl1,
                             const float* __restrict__ Wr1,
                             const float* __restrict__ Wl2,
                             const float* __restrict__ Wr2,
                             const float* __restrict__ Wout) {
    const float* Wm[5] = {Wl1, Wr1, Wl2, Wr2, Wout};
    int m = blockIdx.x;
    const float* W = Wm[m];
    int rows = (m == 4) ? 40 : 128;
    int rows_img = (m == 4) ? 64 : 128;
    char* hi_img = (char*)&g_wimg[2 * m][0];
    char* lo_img = (char*)&g_wimg[2 * m + 1][0];
    for (int g = threadIdx.x; g < rows_img * 16; g += blockDim.x) {
        int row = g >> 4;
        int col8 = (g & 15) << 3;
        float f[8] = {0.f, 0.f, 0.f, 0.f, 0.f, 0.f, 0.f, 0.f};
        if (row < rows) {
            #pragma unroll
            for (int i = 0; i < 8; i++) f[i] = W[row * 128 + col8 + i];
        }
        u32 hp[4], lp[4];
        split8(f, hp, lp);
        int off = row * PITCHB + col8 * 2;
        *reinterpret_cast<uint4*>(hi_img + off) = make_uint4(hp[0], hp[1], hp[2], hp[3]);
        *reinterpret_cast<uint4*>(lo_img + off) = make_uint4(lp[0], lp[1], lp[2], lp[3]);
    }
}

// ---------------------------------------------------------------------------
// PERSISTENT dual GEMM: C = relu(A1@Wl^T + A2@Wr^T + bias).
// grid = min(148, ntiles), 512 threads, warp grid 4x4, warp tile 16x32,
// M-tile 64. B images loaded once; A hi/lo double-buffered.
// ---------------------------------------------------------------------------
__global__ __launch_bounds__(512) void gemm_pers_kernel(
    const float* __restrict__ A1, const float* __restrict__ A2,
    int imgbase, const float* __restrict__ bias,
    float* __restrict__ C, u32* __restrict__ Ch, int n, int ntiles) {
    extern __shared__ __align__(16) char smem[];
    u32 sbase = smem_u32(smem);
    int tid = threadIdx.x, wid = tid >> 5, lane = tid & 31;
    int wr = (wid >> 2) * 16;
    int wc = (wid & 3) * 32;
    int bid = blockIdx.x, G = gridDim.x;

    #pragma unroll
    for (int im = 0; im < 4; im++) {
        const uint4* b = g_wimg[imgbase + im];
        for (int g = tid; g < BIMG / 16; g += 512)
            cpa16(sbase + PB + im * BIMG + g * 16, b + g);
    }
    cpa_commit_wait();

    int ntl = (ntiles > bid) ? (ntiles - bid + G - 1) / G : 0;
    int Wtot = 2 * ntl;
    if (Wtot == 0) return;

    float acc[4][4];
    #pragma unroll
    for (int b = 0; b < 4; b++)
        #pragma unroll
        for (int c = 0; c < 4; c++) acc[b][c] = 0.f;

    conv_slab(A1, bid * 64, n, smem, PA(0), tid, 512);

    int lr = lane & 15;
    int lc = (lane >> 4) * 8;

    #pragma unroll 1
    for (int w = 0; w < Wtot; w++) {
        __syncthreads();
        int p = w & 1;
        int tile = bid + (w >> 1) * G;
        if (w + 1 < Wtot) {
            int p2 = (w + 1) & 1;
            int t2 = bid + ((w + 1) >> 1) * G;
            conv_slab(p2 ? A2 : A1, t2 * 64, n, smem, PA(p2), tid, 512);
        }
        u32 abase = sbase + PA(p);
        u32 bbase = sbase + PB + p * 2 * BIMG;
        #pragma unroll 1
        for (int k0 = 0; k0 < 128; k0 += 16) {
            u32 ah[4], al[4], bh[2][4], bl[2][4];
            u32 ad = abase + (wr + lr) * PITCHB + (k0 + lc) * 2;
            ldsm4(ah[0], ah[1], ah[2], ah[3], ad);
            ldsm4(al[0], al[1], al[2], al[3], ad + AIMG);
            #pragma unroll
            for (int q = 0; q < 2; q++) {
                u32 bd = bbase + (wc + q * 16 + lr) * PITCHB + (k0 + lc) * 2;
                ldsm4(bh[q][0], bh[q][1], bh[q][2], bh[q][3], bd);
                ldsm4(bl[q][0], bl[q][1], bl[q][2], bl[q][3], bd + BIMG);
            }
            #pragma unroll
            for (int nf = 0; nf < 4; nf++) {
                int q = nf >> 1, h = nf & 1;
                mma_bf16(acc[nf], ah, bh[q][h], bh[q][h + 2]);
                mma_bf16(acc[nf], al, bh[q][h], bh[q][h + 2]);
                mma_bf16(acc[nf], ah, bl[q][h], bl[q][h + 2]);
            }
        }
        if (p == 1) {
            int rb = tile * 64 + wr + (lane >> 2);
            #pragma unroll
            for (int nf = 0; nf < 4; nf++) {
                int cn = wc + nf * 8 + (lane & 3) * 2;
                float b0 = __ldg(&bias[cn]), b1 = __ldg(&bias[cn + 1]);
                float v0 = acc[nf][0] + b0, v1 = acc[nf][1] + b1;
                float v2 = acc[nf][2] + b0, v3 = acc[nf][3] + b1;
                v0 = v0 < 0.f ? 0.f : v0; v1 = v1 < 0.f ? 0.f : v1;
                v2 = v2 < 0.f ? 0.f : v2; v3 = v3 < 0.f ? 0.f : v3;
                if (rb < n) {
                    *reinterpret_cast<float2*>(&C[(size_t)rb * 128 + cn]) =
                        make_float2(v0, v1);
                    if (Ch) Ch[(size_t)rb * 64 + (cn >> 1)] =
                        h2bits(__floats2half2_rn(v0, v1));
                }
                if (rb + 8 < n) {
                    *reinterpret_cast<float2*>(&C[(size_t)(rb + 8) * 128 + cn]) =
                        make_float2(v2, v3);
                    if (Ch) Ch[(size_t)(rb + 8) * 64 + (cn >> 1)] =
                        h2bits(__floats2half2_rn(v2, v3));
                }
                acc[nf][0] = acc[nf][1] = acc[nf][2] = acc[nf][3] = 0.f;
            }
        }
    }
}

// ---------------------------------------------------------------------------
// PERSISTENT head: out[N,40] = h2 @ Wout^T + bout (Wout padded to 64 rows).
// grid = min(148, ntiles), 256 threads, warp grid 4x2, warp tile 16x32.
// B loaded once; A double-buffered.
// ---------------------------------------------------------------------------
__global__ __launch_bounds__(256) void head_pers_kernel(
    const float* __restrict__ h, const float* __restrict__ bout,
    float* __restrict__ out, int n, int ntiles) {
    extern __shared__ __align__(16) char smem[];
    u32 sbase = smem_u32(smem);
    int tid = threadIdx.x, wid = tid >> 5, lane = tid & 31;
    int wr = (wid >> 1) * 16;
    int wc = (wid & 1) * 32;
    int bid = blockIdx.x, G = gridDim.x;

    for (int g = tid; g < AIMG / 16; g += 256) {
        cpa16(sbase + H_B + g * 16, &g_wimg[8][g]);
        cpa16(sbase + H_B + AIMG + g * 16, &g_wimg[9][g]);
    }
    cpa_commit_wait();

    int ntl = (ntiles > bid) ? (ntiles - bid + G - 1) / G : 0;
    if (ntl == 0) return;

    conv_slab(h, bid * 64, n, smem, PA(0), tid, 256);

    int lr = lane & 15;
    int lc = (lane >> 4) * 8;

    #pragma unroll 1
    for (int w = 0; w < ntl; w++) {
        __syncthreads();
        int p = w & 1;
        int tile = bid + w * G;
        if (w + 1 < ntl)
            conv_slab(h, (bid + (w + 1) * G) * 64, n, smem, PA((w + 1) & 1),
                      tid, 256);

        float acc[4][4];
        #pragma unroll
        for (int b = 0; b < 4; b++)
            #pragma unroll
            for (int c = 0; c < 4; c++) acc[b][c] = 0.f;

        u32 abase = sbase + PA(p);
        #pragma unroll 1
        for (int k0 = 0; k0 < 128; k0 += 16) {
            u32 ah[4], al[4], bh[2][4], bl[2][4];
            u32 ad = abase + (wr + lr) * PITCHB + (k0 + lc) * 2;
            ldsm4(ah[0], ah[1], ah[2], ah[3], ad);
            ldsm4(al[0], al[1], al[2], al[3], ad + AIMG);
            #pragma unroll
            for (int q = 0; q < 2; q++) {
                u32 bd = sbase + H_B + (wc + q * 16 + lr) * PITCHB + (k0 + lc) * 2;
                ldsm4(bh[q][0], bh[q][1], bh[q][2], bh[q][3], bd);
                ldsm4(bl[q][0], bl[q][1], bl[q][2], bl[q][3], bd + AIMG);
            }
            #pragma unroll
            for (int nf = 0; nf < 4; nf++) {
                int q = nf >> 1, hh = nf & 1;
                mma_bf16(acc[nf], ah, bh[q][hh], bh[q][hh + 2]);
                mma_bf16(acc[nf], al, bh[q][hh], bh[q][hh + 2]);
                mma_bf16(acc[nf], ah, bl[q][hh], bl[q][hh + 2]);
            }
        }

        int rb = tile * 64 + wr + (lane >> 2);
        #pragma unroll
        for (int nf = 0; nf < 4; nf++) {
            int cn = wc + nf * 8 + (lane & 3) * 2;
            if (cn < 40) {
                float b0 = __ldg(&bout[cn]), b1 = __ldg(&bout[cn + 1]);
                if (rb < n)
                    *reinterpret_cast<float2*>(&out[(size_t)rb * 40 + cn]) =
                        make_float2(acc[nf][0] + b0, acc[nf][1] + b1);
                if (rb + 8 < n)
                    *reinterpret_cast<float2*>(&out[(size_t)(rb + 8) * 40 + cn]) =
                        make_float2(acc[nf][2] + b0, acc[nf][3] + b1);
            }
        }
    }
}

// ---------------------------------------------------------------------------
extern "C" void kernel_launch(void* const* d_in, const int* in_sizes, int n_in,
                              void* d_out, int out_size) {
    const float* x = (const float*)d_in[0];
    const void* ei = d_in[1];
    const float* Wl1 = (const float*)d_in[2];
    const float* bl1 = (const float*)d_in[3];
    const float* Wr1 = (const float*)d_in[4];
    const float* Wl2 = (const float*)d_in[5];
    const float* bl2 = (const float*)d_in[6];
    const float* Wr2 = (const float*)d_in[7];
    const float* Wout = (const float*)d_in[8];
    const float* bout = (const float*)d_in[9];
    float* out = (float*)d_out;

    int n = in_sizes[0] / DIM;
    int e = in_sizes[1] / 2;

    static float* mean_f = nullptr;
    static float* h1_f = nullptr;
    static float* h2_f = nullptr;
    static uint2* xh_p = nullptr;
    static uint2* h1h_p = nullptr;
    if (!mean_f) {  // one-time symbol lookup + smem attributes (no allocation)
        void* p;
        cudaGetSymbolAddress(&p, g_mean4); mean_f = (float*)p;
        cudaGetSymbolAddress(&p, g_h14);   h1_f   = (float*)p;
        cudaGetSymbolAddress(&p, g_h24);   h2_f   = (float*)p;
        cudaGetSymbolAddress(&p, g_xh);    xh_p   = (uint2*)p;
        cudaGetSymbolAddress(&p, g_h1h);   h1h_p  = (uint2*)p;
        cudaFuncSetAttribute(gemm_pers_kernel,
                             cudaFuncAttributeMaxDynamicSharedMemorySize, SMEM_PGEMM);
        cudaFuncSetAttribute(head_pers_kernel,
                             cudaFuncAttributeMaxDynamicSharedMemorySize, SMEM_HEAD);
    }

    int eb = (e + 255) / 256;
    int sblk = (n + SCAN_BS - 1) / SCAN_BS;
    int n16 = n * 16;
    int cb = (n16 + 255) / 256;

    prep_kernel<<<cb, 256>>>((const int*)ei, (const float4*)x, e, n, n16);
    hist_kernel<<<eb, 256>>>((const int*)ei, e, n);
    scan_part_kernel<<<sblk, SCAN_BS>>>(n);
    scan_top_kernel<<<1, 1024>>>(sblk, n);
    scan_apply_kernel<<<sblk, SCAN_BS>>>(n);
    scatter_kernel<<<eb, 256>>>((const int*)ei, e, n);
    wprep_kernel<<<5, 256>>>(Wl1, Wr1, Wl2, Wr2, Wout);

    int ab = (n + 7) / 8;
    int ntiles = (n + 63) / 64;
    int pg = (ntiles < 148) ? ntiles : 148;

    // Layer 1 (gather fp16 x; GEMM writes h1 + fp16 copy)
    aggregate_kernel<<<ab, 256>>>(xh_p, (float4*)mean_f, n);
    gemm_pers_kernel<<<pg, 512, SMEM_PGEMM>>>(mean_f, x, 0, bl1, h1_f,
                                              (u32*)h1h_p, n, ntiles);
    // Layer 2 (gather fp16 h1)
    aggregate_kernel<<<ab, 256>>>(h1h_p, (float4*)mean_f, n);
    gemm_pers_kernel<<<pg, 512, SMEM_PGEMM>>>(mean_f, h1_f, 4, bl2, h2_f,
                                              nullptr, n, ntiles);
    // Head (persistent tensor-core)
    head_pers_kernel<<<pg, 256, SMEM_HEAD>>>(h2_f, bout, out, n, ntiles);
}